// round 8
// baseline (speedup 1.0000x reference)
#include <cuda_runtime.h>
#include <cstdint>
#include <math.h>

#define SEQ_    2048
#define DIN_    2048
#define NH_     32
#define NKV_    8
#define HD_     64
#define DQKV_   3072            // Q(2048) | K(512) | V(512) fused columns
#define DOUT_   2048
#define GK_     2048            // GEMM K (both GEMMs have K=2048)

// ---------------------------------------------------------------------------
// Scratch (__device__ globals; allocation-free rule)
// ---------------------------------------------------------------------------
__device__ float g_xr[SEQ_ * DIN_];        // x rounded to tf32 grid
__device__ float g_wt[DQKV_ * DIN_];       // W_qkv^T [3072][2048], tf32-rounded
__device__ float g_wot[DIN_ * DOUT_];      // Wo^T    [2048][2048], tf32-rounded
__device__ float g_QKV[SEQ_ * DQKV_];      // [S, 3072]: Q | K | V
__device__ float g_A[SEQ_ * DOUT_];        // attention out, tf32-rounded

// ---------------------------------------------------------------------------
// Helpers (baseline PTX only — compute_103 has no 'a' features)
// ---------------------------------------------------------------------------
__device__ __forceinline__ uint32_t smem_u32(const void* p) {
    uint32_t a;
    asm("{ .reg .u64 t; cvta.to.shared.u64 t, %1; cvt.u32.u64 %0, t; }" : "=r"(a) : "l"(p));
    return a;
}
__device__ __forceinline__ float rnd_tf32(float f) {
    uint32_t u;
    asm("cvt.rna.tf32.f32 %0, %1;" : "=r"(u) : "f"(f));
    return __uint_as_float(u);
}
__device__ __forceinline__ void cpasync16(uint32_t dst, const void* src) {
    asm volatile("cp.async.cg.shared.global [%0], [%1], 16;" :: "r"(dst), "l"(src));
}
#define CP_COMMIT()  asm volatile("cp.async.commit_group;" ::: "memory")
#define CP_WAIT(n)   asm volatile("cp.async.wait_group %0;" :: "n"(n) : "memory")

__device__ __forceinline__ void mma_tf32(float* d, const float* a, const float* b) {
    asm volatile(
        "mma.sync.aligned.m16n8k8.row.col.f32.tf32.tf32.f32 "
        "{%0,%1,%2,%3}, {%4,%5,%6,%7}, {%8,%9}, {%0,%1,%2,%3};"
        : "+f"(d[0]), "+f"(d[1]), "+f"(d[2]), "+f"(d[3])
        : "r"(__float_as_uint(a[0])), "r"(__float_as_uint(a[1])),
          "r"(__float_as_uint(a[2])), "r"(__float_as_uint(a[3])),
          "r"(__float_as_uint(b[0])), "r"(__float_as_uint(b[1])));
}

// ---------------------------------------------------------------------------
// Prep kernels
// ---------------------------------------------------------------------------
__global__ void cvt_round4(const float* __restrict__ src, float* __restrict__ dst, int n4) {
    int i = blockIdx.x * blockDim.x + threadIdx.x;
    if (i >= n4) return;
    float4 v = ((const float4*)src)[i];
    v.x = rnd_tf32(v.x); v.y = rnd_tf32(v.y);
    v.z = rnd_tf32(v.z); v.w = rnd_tf32(v.w);
    ((float4*)dst)[i] = v;
}

// Transpose + round one weight: W[K=2048, ncols] -> out[(row_off+n)*2048 + k]
__device__ __forceinline__ void tpose_body(const float* __restrict__ W, int ncols,
                                           float* __restrict__ out, int row_off,
                                           int bx, int by) {
    __shared__ float t[32][33];
    int tx = threadIdx.x, ty = threadIdx.y;
    int x = bx * 32 + tx;
    int y = by * 32 + ty;
#pragma unroll
    for (int i = 0; i < 32; i += 8)
        t[ty + i][tx] = W[(size_t)(y + i) * ncols + x];
    __syncthreads();
    int n = bx * 32 + ty;
    int k = by * 32 + tx;
#pragma unroll
    for (int i = 0; i < 32; i += 8)
        out[(size_t)(row_off + n + i) * GK_ + k] = rnd_tf32(t[tx][ty + i]);
}

__global__ void tposer(const float* __restrict__ W, int ncols,
                       float* __restrict__ out, int row_off) {
    tpose_body(W, ncols, out, row_off, blockIdx.x, blockIdx.y);
}

// Fused wq|wk|wv transpose via blockIdx.z (z=0: wq 64 xblocks; z=1,2: wk,wv 16)
__global__ void tposer3(const float* __restrict__ wq, const float* __restrict__ wk,
                        const float* __restrict__ wv, float* __restrict__ out) {
    int z = blockIdx.z;
    if (z == 0) {
        tpose_body(wq, 2048, out, 0, blockIdx.x, blockIdx.y);
    } else if (z == 1) {
        if (blockIdx.x < 16) tpose_body(wk, 512, out, 2048, blockIdx.x, blockIdx.y);
    } else {
        if (blockIdx.x < 16) tpose_body(wv, 512, out, 2560, blockIdx.x, blockIdx.y);
    }
}

// Round the V column region of g_QKV (cols 2560..3071) to tf32 grid, in place
__global__ void round_v() {
    int i = blockIdx.x * blockDim.x + threadIdx.x;   // over 2048*128 float4
    int row = i >> 7, c = i & 127;
    float4* p = (float4*)(g_QKV + (size_t)row * DQKV_ + 2560) + c;
    float4 v = *p;
    v.x = rnd_tf32(v.x); v.y = rnd_tf32(v.y);
    v.z = rnd_tf32(v.z); v.w = rnd_tf32(v.w);
    *p = v;
}

// ---------------------------------------------------------------------------
// tf32 mma.sync GEMM, 3-stage cp.async pipeline.
// C = A[M,2048] @ Bt[N,2048]^T. CTA tile 128x128, BK=32, 8 warps (2x4).
// ---------------------------------------------------------------------------
#define NCH32_  (GK_ / 32)     // 64
#define KPAD_   36
#define STG_F_  (2 * 128 * KPAD_)   // 9216 floats per stage
#define NSTG_   3

__global__ __launch_bounds__(256, 2) void gemm_tf32(
    const float* __restrict__ A, const float* __restrict__ Bt,
    float* __restrict__ C, int ldc)
{
    extern __shared__ float sm[];
    const int tid = threadIdx.x;
    const int wid = tid >> 5, lane = tid & 31;
    const int bm = blockIdx.y * 128, bn = blockIdx.x * 128;
    const int warp_m = (wid & 1) * 64, warp_n = (wid >> 1) * 32;
    const int tr = lane >> 2, tc = lane & 3;

    float acc[4][4][4];
#pragma unroll
    for (int i = 0; i < 4; i++)
#pragma unroll
        for (int j = 0; j < 4; j++)
#pragma unroll
            for (int r = 0; r < 4; r++) acc[i][j][r] = 0.f;

    const float* Ag = A + (size_t)bm * GK_;
    const float* Bg = Bt + (size_t)bn * GK_;
    const int lrow = tid >> 3;
    const int lq = tid & 7;
    uint32_t sbase = smem_u32(sm);

    // issue cp.async for chunk c into stage c%3
    auto issue = [&](int c) {
        uint32_t sA = sbase + (uint32_t)(c % NSTG_) * STG_F_ * 4;
        uint32_t sB = sA + 128 * KPAD_ * 4;
        const int k0 = c * 32;
#pragma unroll
        for (int i = 0; i < 4; i++) {
            int row = lrow + i * 32;
            uint32_t off = (uint32_t)(row * KPAD_ + lq * 4) * 4;
            cpasync16(sA + off, Ag + (size_t)row * GK_ + k0 + lq * 4);
            cpasync16(sB + off, Bg + (size_t)row * GK_ + k0 + lq * 4);
        }
        CP_COMMIT();
    };

    issue(0);
    issue(1);

    for (int c = 0; c < NCH32_; c++) {
        if (c + 2 < NCH32_) { issue(c + 2); CP_WAIT(2); }
        else if (c + 1 < NCH32_) CP_WAIT(1);
        else CP_WAIT(0);
        __syncthreads();

        const float* As = sm + (c % NSTG_) * STG_F_;
        const float* Bs = As + 128 * KPAD_;

#pragma unroll
        for (int kk = 0; kk < 4; kk++) {
            const int kb = kk * 8;
            float a[4][4], b[4][2];
#pragma unroll
            for (int mt = 0; mt < 4; mt++) {
                const float* ap = As + (warp_m + mt * 16 + tr) * KPAD_ + kb + tc;
                a[mt][0] = ap[0];
                a[mt][1] = ap[8 * KPAD_];
                a[mt][2] = ap[4];
                a[mt][3] = ap[8 * KPAD_ + 4];
            }
#pragma unroll
            for (int nt = 0; nt < 4; nt++) {
                const float* bp = Bs + (warp_n + nt * 8 + tr) * KPAD_ + kb + tc;
                b[nt][0] = bp[0];
                b[nt][1] = bp[4];
            }
#pragma unroll
            for (int mt = 0; mt < 4; mt++)
#pragma unroll
                for (int nt = 0; nt < 4; nt++)
                    mma_tf32(acc[mt][nt], a[mt], b[nt]);
        }
        __syncthreads();
    }

#pragma unroll
    for (int mt = 0; mt < 4; mt++)
#pragma unroll
        for (int nt = 0; nt < 4; nt++) {
            int row = bm + warp_m + mt * 16 + tr;
            int col = bn + warp_n + nt * 8 + 2 * tc;
            *(float2*)(C + (size_t)row * ldc + col) =
                make_float2(acc[mt][nt][0], acc[mt][nt][1]);
            *(float2*)(C + (size_t)(row + 8) * ldc + col) =
                make_float2(acc[mt][nt][2], acc[mt][nt][3]);
        }
}

// ---------------------------------------------------------------------------
// Fused RMSNorm + RoPE, in place; optional tf32 rounding of results (for K).
// ---------------------------------------------------------------------------
__global__ void norm_rope(float* __restrict__ X, const float* __restrict__ w,
                          const float* __restrict__ cosp, const float* __restrict__ sinp,
                          int nheads, int rowdim, int do_round) {
    int gwarp = (blockIdx.x * blockDim.x + threadIdx.x) >> 5;
    int lane = threadIdx.x & 31;
    int s = gwarp / nheads;
    int h = gwarp % nheads;
    if (s >= SEQ_) return;

    float* p = X + (size_t)s * rowdim + h * HD_;
    float x0 = p[lane];
    float x1 = p[lane + 32];

    float ss = x0 * x0 + x1 * x1;
#pragma unroll
    for (int off = 16; off; off >>= 1) ss += __shfl_xor_sync(0xFFFFFFFFu, ss, off);
    float r = rsqrtf(ss * (1.f / 64.f) + 1e-6f);

    x0 = x0 * r * w[lane];
    x1 = x1 * r * w[lane + 32];

    float c0 = cosp[s * HD_ + lane],      s0 = sinp[s * HD_ + lane];
    float c1 = cosp[s * HD_ + lane + 32], s1 = sinp[s * HD_ + lane + 32];

    float y0 = x0 * c0 - x1 * s0;
    float y1 = x1 * c1 + x0 * s1;
    if (do_round) { y0 = rnd_tf32(y0); y1 = rnd_tf32(y1); }
    p[lane]      = y0;
    p[lane + 32] = y1;
}

// ---------------------------------------------------------------------------
// Tensor-core causal GQA flash attention (tf32 mma.sync).
// CTA = (q-block of 128, head). 8 warps, 16 q-rows each.
// ---------------------------------------------------------------------------
#define QS_ST  68
#define PS_ST  36
#define KS_ST  68
#define VS_ST  72
#define OFF_K  (128 * QS_ST)
#define OFF_V  (OFF_K + 2 * 32 * KS_ST)
#define FA_SMF (OFF_V + 2 * 32 * VS_ST)      // 17664 floats = 70656 B

__global__ __launch_bounds__(256, 2) void flash_mma() {
    extern __shared__ float sm[];
    const int tid = threadIdx.x;
    const int w = tid >> 5, lane = tid & 31;
    const int tr = lane >> 2, tc = lane & 3;
    const int h = blockIdx.y;
    const int q0 = blockIdx.x * 128;
    const int kvh = h >> 2;

    float* Qs = sm;
    float* Ps = sm;
    float* Ks = sm + OFF_K;
    float* Vs = sm + OFF_V;
    const uint32_t sb = smem_u32(sm);

    {
        const float* Qg = g_QKV + (size_t)q0 * DQKV_ + h * HD_;
#pragma unroll
        for (int i = 0; i < 8; i++) {
            int idx = tid + i * 256;
            int row = idx >> 4, c4 = idx & 15;
            *(float4*)&Qs[row * QS_ST + c4 * 4] =
                *(const float4*)(Qg + (size_t)row * DQKV_ + c4 * 4);
        }
    }
    __syncthreads();

    float q[8][4];
    {
        const float* qp = Qs + (w * 16 + tr) * QS_ST + tc;
#pragma unroll
        for (int ks = 0; ks < 8; ks++) {
            q[ks][0] = rnd_tf32(qp[ks * 8] * 0.125f);
            q[ks][1] = rnd_tf32(qp[8 * QS_ST + ks * 8] * 0.125f);
            q[ks][2] = rnd_tf32(qp[ks * 8 + 4] * 0.125f);
            q[ks][3] = rnd_tf32(qp[8 * QS_ST + ks * 8 + 4] * 0.125f);
        }
    }
    __syncthreads();

    float o[8][4];
#pragma unroll
    for (int nf = 0; nf < 8; nf++)
#pragma unroll
        for (int r = 0; r < 4; r++) o[nf][r] = 0.f;
    float m0 = -1e30f, m1 = -1e30f, l0 = 0.f, l1 = 0.f;

    const int ntiles = (q0 + 128) / 32;
    const float* Kg = g_QKV + 2048 + kvh * HD_;
    const float* Vg = g_QKV + 2560 + kvh * HD_;

    {
#pragma unroll
        for (int j = 0; j < 2; j++) {
            int ci = tid + j * 256;
            int r = ci >> 4, q4 = ci & 15;
            cpasync16(sb + (OFF_K + r * KS_ST + q4 * 4) * 4,
                      Kg + (size_t)r * DQKV_ + q4 * 4);
            cpasync16(sb + (OFF_V + r * VS_ST + q4 * 4) * 4,
                      Vg + (size_t)r * DQKV_ + q4 * 4);
        }
        CP_COMMIT();
    }

    for (int t = 0; t < ntiles; t++) {
        const int k0 = t * 32;
        if (t + 1 < ntiles) {
            const int kn = (t + 1) * 32;
            const int buf = (t + 1) & 1;
#pragma unroll
            for (int j = 0; j < 2; j++) {
                int ci = tid + j * 256;
                int r = ci >> 4, q4 = ci & 15;
                cpasync16(sb + (OFF_K + (buf * 32 + r) * KS_ST + q4 * 4) * 4,
                          Kg + (size_t)(kn + r) * DQKV_ + q4 * 4);
                cpasync16(sb + (OFF_V + (buf * 32 + r) * VS_ST + q4 * 4) * 4,
                          Vg + (size_t)(kn + r) * DQKV_ + q4 * 4);
            }
            CP_COMMIT();
            CP_WAIT(1);
        } else {
            CP_WAIT(0);
        }
        __syncthreads();

        if (k0 <= q0 + w * 16 + 15) {
            const float* Kt = Ks + (t & 1) * 32 * KS_ST;
            const float* Vt = Vs + (t & 1) * 32 * VS_ST;

            float s[4][4];
#pragma unroll
            for (int nf = 0; nf < 4; nf++) {
                s[nf][0] = s[nf][1] = s[nf][2] = s[nf][3] = 0.f;
                const float* bp = Kt + (nf * 8 + tr) * KS_ST + tc;
#pragma unroll
                for (int ks = 0; ks < 8; ks++) {
                    float b[2] = { bp[ks * 8], bp[ks * 8 + 4] };
                    mma_tf32(s[nf], q[ks], b);
                }
            }

            if (k0 + 31 > q0 + w * 16) {
                const int r0 = q0 + w * 16 + tr, r1 = r0 + 8;
                const int cb = k0 + 2 * tc;
#pragma unroll
                for (int nf = 0; nf < 4; nf++) {
                    int c0 = cb + nf * 8, c1 = c0 + 1;
                    if (c0 > r0) s[nf][0] = -1e30f;
                    if (c1 > r0) s[nf][1] = -1e30f;
                    if (c0 > r1) s[nf][2] = -1e30f;
                    if (c1 > r1) s[nf][3] = -1e30f;
                }
            }

            float t0 = fmaxf(fmaxf(s[0][0], s[0][1]), fmaxf(s[1][0], s[1][1]));
            t0 = fmaxf(t0, fmaxf(fmaxf(s[2][0], s[2][1]), fmaxf(s[3][0], s[3][1])));
            float t1 = fmaxf(fmaxf(s[0][2], s[0][3]), fmaxf(s[1][2], s[1][3]));
            t1 = fmaxf(t1, fmaxf(fmaxf(s[2][2], s[2][3]), fmaxf(s[3][2], s[3][3])));
            t0 = fmaxf(t0, __shfl_xor_sync(0xFFFFFFFFu, t0, 1));
            t0 = fmaxf(t0, __shfl_xor_sync(0xFFFFFFFFu, t0, 2));
            t1 = fmaxf(t1, __shfl_xor_sync(0xFFFFFFFFu, t1, 1));
            t1 = fmaxf(t1, __shfl_xor_sync(0xFFFFFFFFu, t1, 2));
            const float mt0 = fmaxf(m0, t0), mt1 = fmaxf(m1, t1);
            const float corr0 = __expf(m0 - mt0), corr1 = __expf(m1 - mt1);
            m0 = mt0; m1 = mt1;

            float* prow0 = Ps + (w * 16 + tr) * PS_ST + 2 * tc;
            float* prow1 = prow0 + 8 * PS_ST;
            float sum0 = 0.f, sum1 = 0.f;
#pragma unroll
            for (int nf = 0; nf < 4; nf++) {
                float p0 = rnd_tf32(__expf(s[nf][0] - mt0));
                float p1 = rnd_tf32(__expf(s[nf][1] - mt0));
                float p2 = rnd_tf32(__expf(s[nf][2] - mt1));
                float p3 = rnd_tf32(__expf(s[nf][3] - mt1));
                sum0 += p0 + p1; sum1 += p2 + p3;
                *(float2*)(prow0 + nf * 8) = make_float2(p0, p1);
                *(float2*)(prow1 + nf * 8) = make_float2(p2, p3);
            }
            sum0 += __shfl_xor_sync(0xFFFFFFFFu, sum0, 1);
            sum0 += __shfl_xor_sync(0xFFFFFFFFu, sum0, 2);
            sum1 += __shfl_xor_sync(0xFFFFFFFFu, sum1, 1);
            sum1 += __shfl_xor_sync(0xFFFFFFFFu, sum1, 2);
            l0 = l0 * corr0 + sum0;
            l1 = l1 * corr1 + sum1;

#pragma unroll
            for (int nf = 0; nf < 8; nf++) {
                o[nf][0] *= corr0; o[nf][1] *= corr0;
                o[nf][2] *= corr1; o[nf][3] *= corr1;
            }
            __syncwarp();

            const float* pa = Ps + (w * 16 + tr) * PS_ST + tc;
#pragma unroll
            for (int ks = 0; ks < 4; ks++) {
                float a[4] = { pa[ks * 8], pa[8 * PS_ST + ks * 8],
                               pa[ks * 8 + 4], pa[8 * PS_ST + ks * 8 + 4] };
                const float* vb = Vt + (ks * 8 + tc) * VS_ST + tr;
#pragma unroll
                for (int nf = 0; nf < 8; nf++) {
                    float b[2] = { vb[nf * 8], vb[4 * VS_ST + nf * 8] };
                    mma_tf32(o[nf], a, b);
                }
            }
            __syncwarp();
        }
        __syncthreads();
    }

    const float inv0 = 1.f / l0, inv1 = 1.f / l1;
    const int r0 = q0 + w * 16 + tr;
    float* Og = g_A + (size_t)r0 * DOUT_ + h * HD_ + 2 * tc;
#pragma unroll
    for (int nf = 0; nf < 8; nf++) {
        *(float2*)(Og + nf * 8) =
            make_float2(rnd_tf32(o[nf][0] * inv0), rnd_tf32(o[nf][1] * inv0));
        *(float2*)(Og + 8 * DOUT_ + nf * 8) =
            make_float2(rnd_tf32(o[nf][2] * inv1), rnd_tf32(o[nf][3] * inv1));
    }
}

// ---------------------------------------------------------------------------
extern "C" void kernel_launch(void* const* d_in, const int* in_sizes, int n_in,
                              void* d_out, int out_size) {
    const float* x    = (const float*)d_in[0];
    const float* cosp = (const float*)d_in[1];
    const float* sinp = (const float*)d_in[2];
    const float* wq   = (const float*)d_in[3];
    const float* wk   = (const float*)d_in[4];
    const float* wv   = (const float*)d_in[5];
    const float* wo   = (const float*)d_in[6];
    const float* qw   = (const float*)d_in[7];
    const float* kw   = (const float*)d_in[8];
    float* out = (float*)d_out;

    float *xr, *wt, *wot, *QKV, *A;
    cudaGetSymbolAddress((void**)&xr,  g_xr);
    cudaGetSymbolAddress((void**)&wt,  g_wt);
    cudaGetSymbolAddress((void**)&wot, g_wot);
    cudaGetSymbolAddress((void**)&QKV, g_QKV);
    cudaGetSymbolAddress((void**)&A,   g_A);

    const int smem_sz = NSTG_ * STG_F_ * 4;   // 110592 B
    cudaFuncSetAttribute(gemm_tf32, cudaFuncAttributeMaxDynamicSharedMemorySize, smem_sz);
    const int fa_smem = FA_SMF * 4;           // 70656 B
    cudaFuncSetAttribute(flash_mma, cudaFuncAttributeMaxDynamicSharedMemorySize, fa_smem);

    // Prep: round x; transpose+round weights
    cvt_round4<<<(SEQ_ * DIN_ / 4 + 255) / 256, 256>>>(x, xr, SEQ_ * DIN_ / 4);
    tposer3<<<dim3(64, DIN_ / 32, 3), dim3(32, 8)>>>(wq, wk, wv, wt);
    tposer<<<dim3(2048 / 32, DOUT_ / 32), dim3(32, 8)>>>(wo, 2048, wot, 0);

    // Fused QKV projection (tf32 tensor cores)
    gemm_tf32<<<dim3(DQKV_ / 128, SEQ_ / 128), 256, smem_sz>>>(xr, wt, QKV, DQKV_);

    // RMSNorm + RoPE (K rounded to tf32 in-pass); round V region
    norm_rope<<<(SEQ_ * NH_ * 32) / 256, 256>>>(QKV, qw, cosp, sinp, NH_, DQKV_, 0);
    norm_rope<<<(SEQ_ * NKV_ * 32) / 256, 256>>>(QKV + 2048, kw, cosp, sinp, NKV_, DQKV_, 1);
    round_v<<<SEQ_ * 128 / 256, 256>>>();

    // Tensor-core causal GQA attention
    flash_mma<<<dim3(SEQ_ / 128, NH_), 256, fa_smem>>>();

    // Output projection (tf32 tensor cores)
    gemm_tf32<<<dim3(DIN_ / 128, SEQ_ / 128), 256, smem_sz>>>(A, wot, out, DIN_);
}

// round 10
// speedup vs baseline: 1.0193x; 1.0193x over previous
#include <cuda_runtime.h>
#include <cstdint>
#include <math.h>

#define SEQ_    2048
#define DIN_    2048
#define NH_     32
#define NKV_    8
#define HD_     64
#define DQKV_   3072            // Q(2048) | K(512) | V(512) fused columns
#define DOUT_   2048
#define GK_     2048            // GEMM K (both GEMMs have K=2048)

// ---------------------------------------------------------------------------
// Scratch (__device__ globals; allocation-free rule)
// ---------------------------------------------------------------------------
__device__ float g_xr[SEQ_ * DIN_];        // x rounded to tf32 grid
__device__ float g_wt[DQKV_ * DIN_];       // W_qkv^T [3072][2048], tf32-rounded
__device__ float g_wot[DIN_ * DOUT_];      // Wo^T    [2048][2048], tf32-rounded
__device__ float g_QKV[SEQ_ * DQKV_];      // [S, 3072]: Q | K | V
__device__ float g_A[SEQ_ * DOUT_];        // attention out, tf32-rounded

// ---------------------------------------------------------------------------
// Helpers (baseline PTX only — compute_103 has no 'a' features)
// ---------------------------------------------------------------------------
__device__ __forceinline__ uint32_t smem_u32(const void* p) {
    uint32_t a;
    asm("{ .reg .u64 t; cvta.to.shared.u64 t, %1; cvt.u32.u64 %0, t; }" : "=r"(a) : "l"(p));
    return a;
}
__device__ __forceinline__ float rnd_tf32(float f) {
    uint32_t u;
    asm("cvt.rna.tf32.f32 %0, %1;" : "=r"(u) : "f"(f));
    return __uint_as_float(u);
}
__device__ __forceinline__ void cpasync16(uint32_t dst, const void* src) {
    asm volatile("cp.async.cg.shared.global [%0], [%1], 16;" :: "r"(dst), "l"(src));
}
#define CP_COMMIT()  asm volatile("cp.async.commit_group;" ::: "memory")
#define CP_WAIT(n)   asm volatile("cp.async.wait_group %0;" :: "n"(n) : "memory")

__device__ __forceinline__ void mma_tf32(float* d, const float* a, const float* b) {
    asm volatile(
        "mma.sync.aligned.m16n8k8.row.col.f32.tf32.tf32.f32 "
        "{%0,%1,%2,%3}, {%4,%5,%6,%7}, {%8,%9}, {%0,%1,%2,%3};"
        : "+f"(d[0]), "+f"(d[1]), "+f"(d[2]), "+f"(d[3])
        : "r"(__float_as_uint(a[0])), "r"(__float_as_uint(a[1])),
          "r"(__float_as_uint(a[2])), "r"(__float_as_uint(a[3])),
          "r"(__float_as_uint(b[0])), "r"(__float_as_uint(b[1])));
}

// ---------------------------------------------------------------------------
// Prep kernels
// ---------------------------------------------------------------------------
__global__ void cvt_round4(const float* __restrict__ src, float* __restrict__ dst, int n4) {
    int i = blockIdx.x * blockDim.x + threadIdx.x;
    if (i >= n4) return;
    float4 v = ((const float4*)src)[i];
    v.x = rnd_tf32(v.x); v.y = rnd_tf32(v.y);
    v.z = rnd_tf32(v.z); v.w = rnd_tf32(v.w);
    ((float4*)dst)[i] = v;
}

// Transpose + round one weight: W[K=2048, ncols] -> out[(row_off+n)*2048 + k]
__device__ __forceinline__ void tpose_body(const float* __restrict__ W, int ncols,
                                           float* __restrict__ out, int row_off,
                                           int bx, int by) {
    __shared__ float t[32][33];
    int tx = threadIdx.x, ty = threadIdx.y;
    int x = bx * 32 + tx;
    int y = by * 32 + ty;
#pragma unroll
    for (int i = 0; i < 32; i += 8)
        t[ty + i][tx] = W[(size_t)(y + i) * ncols + x];
    __syncthreads();
    int n = bx * 32 + ty;
    int k = by * 32 + tx;
#pragma unroll
    for (int i = 0; i < 32; i += 8)
        out[(size_t)(row_off + n + i) * GK_ + k] = rnd_tf32(t[tx][ty + i]);
}

__global__ void tposer(const float* __restrict__ W, int ncols,
                       float* __restrict__ out, int row_off) {
    tpose_body(W, ncols, out, row_off, blockIdx.x, blockIdx.y);
}

// Fused wq|wk|wv transpose via blockIdx.z
__global__ void tposer3(const float* __restrict__ wq, const float* __restrict__ wk,
                        const float* __restrict__ wv, float* __restrict__ out) {
    int z = blockIdx.z;
    if (z == 0) {
        tpose_body(wq, 2048, out, 0, blockIdx.x, blockIdx.y);
    } else if (z == 1) {
        if (blockIdx.x < 16) tpose_body(wk, 512, out, 2048, blockIdx.x, blockIdx.y);
    } else {
        if (blockIdx.x < 16) tpose_body(wv, 512, out, 2560, blockIdx.x, blockIdx.y);
    }
}

// Round the V column region of g_QKV (cols 2560..3071) to tf32 grid, in place
__global__ void round_v() {
    int i = blockIdx.x * blockDim.x + threadIdx.x;   // over 2048*128 float4
    int row = i >> 7, c = i & 127;
    float4* p = (float4*)(g_QKV + (size_t)row * DQKV_ + 2560) + c;
    float4 v = *p;
    v.x = rnd_tf32(v.x); v.y = rnd_tf32(v.y);
    v.z = rnd_tf32(v.z); v.w = rnd_tf32(v.w);
    *p = v;
}

// ---------------------------------------------------------------------------
// tf32 mma.sync GEMM, warp tile 64x64 (crossbar-relief config).
// C = A[M,2048] @ Bt[N,2048]^T. CTA tile 128x128, BK=32, 4 warps (2x2),
// 128 threads, 3-stage cp.async, single barrier per chunk.
// ---------------------------------------------------------------------------
#define NCH32_  (GK_ / 32)     // 64
#define KPAD_   36
#define STG_F_  (2 * 128 * KPAD_)   // 9216 floats per stage
#define NSTG_   3

__global__ __launch_bounds__(128, 2) void gemm_tf32(
    const float* __restrict__ A, const float* __restrict__ Bt,
    float* __restrict__ C, int ldc)
{
    extern __shared__ float sm[];
    const int tid = threadIdx.x;
    const int w = tid >> 5, lane = tid & 31;
    const int bm = blockIdx.y * 128, bn = blockIdx.x * 128;
    const int warp_m = (w & 1) * 64, warp_n = (w >> 1) * 64;
    const int tr = lane >> 2, tc = lane & 3;

    float acc[4][8][4];
#pragma unroll
    for (int i = 0; i < 4; i++)
#pragma unroll
        for (int j = 0; j < 8; j++)
#pragma unroll
            for (int r = 0; r < 4; r++) acc[i][j][r] = 0.f;

    const float* Ag = A + (size_t)bm * GK_;
    const float* Bg = Bt + (size_t)bn * GK_;
    const int lrow = tid >> 3;              // 0..15, rows via +=16
    const int lq = tid & 7;
    uint32_t sbase = smem_u32(sm);

    auto issue = [&](int c) {
        uint32_t sA = sbase + (uint32_t)(c % NSTG_) * STG_F_ * 4;
        uint32_t sB = sA + 128 * KPAD_ * 4;
        const int k0 = c * 32;
#pragma unroll
        for (int i = 0; i < 8; i++) {
            int row = lrow + i * 16;
            uint32_t off = (uint32_t)(row * KPAD_ + lq * 4) * 4;
            cpasync16(sA + off, Ag + (size_t)row * GK_ + k0 + lq * 4);
            cpasync16(sB + off, Bg + (size_t)row * GK_ + k0 + lq * 4);
        }
        CP_COMMIT();
    };

    issue(0);
    issue(1);

    for (int c = 0; c < NCH32_; c++) {
        CP_WAIT(1);
        __syncthreads();
        if (c + 2 < NCH32_) issue(c + 2);

        const float* As = sm + (c % NSTG_) * STG_F_;
        const float* Bs = As + 128 * KPAD_;

#pragma unroll
        for (int kk = 0; kk < 4; kk++) {
            const int kb = kk * 8;
            float a[4][4], b[8][2];
#pragma unroll
            for (int mt = 0; mt < 4; mt++) {
                const float* ap = As + (warp_m + mt * 16 + tr) * KPAD_ + kb + tc;
                a[mt][0] = ap[0];
                a[mt][1] = ap[8 * KPAD_];
                a[mt][2] = ap[4];
                a[mt][3] = ap[8 * KPAD_ + 4];
            }
#pragma unroll
            for (int nt = 0; nt < 8; nt++) {
                const float* bp = Bs + (warp_n + nt * 8 + tr) * KPAD_ + kb + tc;
                b[nt][0] = bp[0];
                b[nt][1] = bp[4];
            }
#pragma unroll
            for (int mt = 0; mt < 4; mt++)
#pragma unroll
                for (int nt = 0; nt < 8; nt++)
                    mma_tf32(acc[mt][nt], a[mt], b[nt]);
        }
    }
    // NOTE: no trailing barrier needed — epilogue only reads registers.

#pragma unroll
    for (int mt = 0; mt < 4; mt++)
#pragma unroll
        for (int nt = 0; nt < 8; nt++) {
            int row = bm + warp_m + mt * 16 + tr;
            int col = bn + warp_n + nt * 8 + 2 * tc;
            *(float2*)(C + (size_t)row * ldc + col) =
                make_float2(acc[mt][nt][0], acc[mt][nt][1]);
            *(float2*)(C + (size_t)(row + 8) * ldc + col) =
                make_float2(acc[mt][nt][2], acc[mt][nt][3]);
        }
}

// ---------------------------------------------------------------------------
// Fused RMSNorm + RoPE, in place; optional tf32 rounding of results (for K).
// ---------------------------------------------------------------------------
__global__ void norm_rope(float* __restrict__ X, const float* __restrict__ w,
                          const float* __restrict__ cosp, const float* __restrict__ sinp,
                          int nheads, int rowdim, int do_round) {
    int gwarp = (blockIdx.x * blockDim.x + threadIdx.x) >> 5;
    int lane = threadIdx.x & 31;
    int s = gwarp / nheads;
    int h = gwarp % nheads;
    if (s >= SEQ_) return;

    float* p = X + (size_t)s * rowdim + h * HD_;
    float x0 = p[lane];
    float x1 = p[lane + 32];

    float ss = x0 * x0 + x1 * x1;
#pragma unroll
    for (int off = 16; off; off >>= 1) ss += __shfl_xor_sync(0xFFFFFFFFu, ss, off);
    float r = rsqrtf(ss * (1.f / 64.f) + 1e-6f);

    x0 = x0 * r * w[lane];
    x1 = x1 * r * w[lane + 32];

    float c0 = cosp[s * HD_ + lane],      s0 = sinp[s * HD_ + lane];
    float c1 = cosp[s * HD_ + lane + 32], s1 = sinp[s * HD_ + lane + 32];

    float y0 = x0 * c0 - x1 * s0;
    float y1 = x1 * c1 + x0 * s1;
    if (do_round) { y0 = rnd_tf32(y0); y1 = rnd_tf32(y1); }
    p[lane]      = y0;
    p[lane + 32] = y1;
}

// ---------------------------------------------------------------------------
// Tensor-core causal GQA flash attention (tf32 mma.sync).
// CTA = (q-block of 128, head). 8 warps, 16 q-rows each.
// ---------------------------------------------------------------------------
#define QS_ST  68
#define PS_ST  36
#define KS_ST  68
#define VS_ST  72
#define OFF_K  (128 * QS_ST)
#define OFF_V  (OFF_K + 2 * 32 * KS_ST)
#define FA_SMF (OFF_V + 2 * 32 * VS_ST)      // 17664 floats = 70656 B

__global__ __launch_bounds__(256, 2) void flash_mma() {
    extern __shared__ float sm[];
    const int tid = threadIdx.x;
    const int w = tid >> 5, lane = tid & 31;
    const int tr = lane >> 2, tc = lane & 3;
    const int h = blockIdx.y;
    const int q0 = blockIdx.x * 128;
    const int kvh = h >> 2;

    float* Qs = sm;
    float* Ps = sm;
    float* Ks = sm + OFF_K;
    float* Vs = sm + OFF_V;
    const uint32_t sb = smem_u32(sm);

    {
        const float* Qg = g_QKV + (size_t)q0 * DQKV_ + h * HD_;
#pragma unroll
        for (int i = 0; i < 8; i++) {
            int idx = tid + i * 256;
            int row = idx >> 4, c4 = idx & 15;
            *(float4*)&Qs[row * QS_ST + c4 * 4] =
                *(const float4*)(Qg + (size_t)row * DQKV_ + c4 * 4);
        }
    }
    __syncthreads();

    float q[8][4];
    {
        const float* qp = Qs + (w * 16 + tr) * QS_ST + tc;
#pragma unroll
        for (int ks = 0; ks < 8; ks++) {
            q[ks][0] = rnd_tf32(qp[ks * 8] * 0.125f);
            q[ks][1] = rnd_tf32(qp[8 * QS_ST + ks * 8] * 0.125f);
            q[ks][2] = rnd_tf32(qp[ks * 8 + 4] * 0.125f);
            q[ks][3] = rnd_tf32(qp[8 * QS_ST + ks * 8 + 4] * 0.125f);
        }
    }
    __syncthreads();

    float o[8][4];
#pragma unroll
    for (int nf = 0; nf < 8; nf++)
#pragma unroll
        for (int r = 0; r < 4; r++) o[nf][r] = 0.f;
    float m0 = -1e30f, m1 = -1e30f, l0 = 0.f, l1 = 0.f;

    const int ntiles = (q0 + 128) / 32;
    const float* Kg = g_QKV + 2048 + kvh * HD_;
    const float* Vg = g_QKV + 2560 + kvh * HD_;

    {
#pragma unroll
        for (int j = 0; j < 2; j++) {
            int ci = tid + j * 256;
            int r = ci >> 4, q4 = ci & 15;
            cpasync16(sb + (OFF_K + r * KS_ST + q4 * 4) * 4,
                      Kg + (size_t)r * DQKV_ + q4 * 4);
            cpasync16(sb + (OFF_V + r * VS_ST + q4 * 4) * 4,
                      Vg + (size_t)r * DQKV_ + q4 * 4);
        }
        CP_COMMIT();
    }

    for (int t = 0; t < ntiles; t++) {
        const int k0 = t * 32;
        if (t + 1 < ntiles) {
            const int kn = (t + 1) * 32;
            const int buf = (t + 1) & 1;
#pragma unroll
            for (int j = 0; j < 2; j++) {
                int ci = tid + j * 256;
                int r = ci >> 4, q4 = ci & 15;
                cpasync16(sb + (OFF_K + (buf * 32 + r) * KS_ST + q4 * 4) * 4,
                          Kg + (size_t)(kn + r) * DQKV_ + q4 * 4);
                cpasync16(sb + (OFF_V + (buf * 32 + r) * VS_ST + q4 * 4) * 4,
                          Vg + (size_t)(kn + r) * DQKV_ + q4 * 4);
            }
            CP_COMMIT();
            CP_WAIT(1);
        } else {
            CP_WAIT(0);
        }
        __syncthreads();

        if (k0 <= q0 + w * 16 + 15) {
            const float* Kt = Ks + (t & 1) * 32 * KS_ST;
            const float* Vt = Vs + (t & 1) * 32 * VS_ST;

            float s[4][4];
#pragma unroll
            for (int nf = 0; nf < 4; nf++) {
                s[nf][0] = s[nf][1] = s[nf][2] = s[nf][3] = 0.f;
                const float* bp = Kt + (nf * 8 + tr) * KS_ST + tc;
#pragma unroll
                for (int ks = 0; ks < 8; ks++) {
                    float b[2] = { bp[ks * 8], bp[ks * 8 + 4] };
                    mma_tf32(s[nf], q[ks], b);
                }
            }

            if (k0 + 31 > q0 + w * 16) {
                const int r0 = q0 + w * 16 + tr, r1 = r0 + 8;
                const int cb = k0 + 2 * tc;
#pragma unroll
                for (int nf = 0; nf < 4; nf++) {
                    int c0 = cb + nf * 8, c1 = c0 + 1;
                    if (c0 > r0) s[nf][0] = -1e30f;
                    if (c1 > r0) s[nf][1] = -1e30f;
                    if (c0 > r1) s[nf][2] = -1e30f;
                    if (c1 > r1) s[nf][3] = -1e30f;
                }
            }

            float t0 = fmaxf(fmaxf(s[0][0], s[0][1]), fmaxf(s[1][0], s[1][1]));
            t0 = fmaxf(t0, fmaxf(fmaxf(s[2][0], s[2][1]), fmaxf(s[3][0], s[3][1])));
            float t1 = fmaxf(fmaxf(s[0][2], s[0][3]), fmaxf(s[1][2], s[1][3]));
            t1 = fmaxf(t1, fmaxf(fmaxf(s[2][2], s[2][3]), fmaxf(s[3][2], s[3][3])));
            t0 = fmaxf(t0, __shfl_xor_sync(0xFFFFFFFFu, t0, 1));
            t0 = fmaxf(t0, __shfl_xor_sync(0xFFFFFFFFu, t0, 2));
            t1 = fmaxf(t1, __shfl_xor_sync(0xFFFFFFFFu, t1, 1));
            t1 = fmaxf(t1, __shfl_xor_sync(0xFFFFFFFFu, t1, 2));
            const float mt0 = fmaxf(m0, t0), mt1 = fmaxf(m1, t1);
            const float corr0 = __expf(m0 - mt0), corr1 = __expf(m1 - mt1);
            m0 = mt0; m1 = mt1;

            float* prow0 = Ps + (w * 16 + tr) * PS_ST + 2 * tc;
            float* prow1 = prow0 + 8 * PS_ST;
            float sum0 = 0.f, sum1 = 0.f;
#pragma unroll
            for (int nf = 0; nf < 4; nf++) {
                float p0 = rnd_tf32(__expf(s[nf][0] - mt0));
                float p1 = rnd_tf32(__expf(s[nf][1] - mt0));
                float p2 = rnd_tf32(__expf(s[nf][2] - mt1));
                float p3 = rnd_tf32(__expf(s[nf][3] - mt1));
                sum0 += p0 + p1; sum1 += p2 + p3;
                *(float2*)(prow0 + nf * 8) = make_float2(p0, p1);
                *(float2*)(prow1 + nf * 8) = make_float2(p2, p3);
            }
            sum0 += __shfl_xor_sync(0xFFFFFFFFu, sum0, 1);
            sum0 += __shfl_xor_sync(0xFFFFFFFFu, sum0, 2);
            sum1 += __shfl_xor_sync(0xFFFFFFFFu, sum1, 1);
            sum1 += __shfl_xor_sync(0xFFFFFFFFu, sum1, 2);
            l0 = l0 * corr0 + sum0;
            l1 = l1 * corr1 + sum1;

#pragma unroll
            for (int nf = 0; nf < 8; nf++) {
                o[nf][0] *= corr0; o[nf][1] *= corr0;
                o[nf][2] *= corr1; o[nf][3] *= corr1;
            }
            __syncwarp();

            const float* pa = Ps + (w * 16 + tr) * PS_ST + tc;
#pragma unroll
            for (int ks = 0; ks < 4; ks++) {
                float a[4] = { pa[ks * 8], pa[8 * PS_ST + ks * 8],
                               pa[ks * 8 + 4], pa[8 * PS_ST + ks * 8 + 4] };
                const float* vb = Vt + (ks * 8 + tc) * VS_ST + tr;
#pragma unroll
                for (int nf = 0; nf < 8; nf++) {
                    float b[2] = { vb[nf * 8], vb[4 * VS_ST + nf * 8] };
                    mma_tf32(o[nf], a, b);
                }
            }
            __syncwarp();
        }
        __syncthreads();
    }

    const float inv0 = 1.f / l0, inv1 = 1.f / l1;
    const int r0 = q0 + w * 16 + tr;
    float* Og = g_A + (size_t)r0 * DOUT_ + h * HD_ + 2 * tc;
#pragma unroll
    for (int nf = 0; nf < 8; nf++) {
        *(float2*)(Og + nf * 8) =
            make_float2(rnd_tf32(o[nf][0] * inv0), rnd_tf32(o[nf][1] * inv0));
        *(float2*)(Og + 8 * DOUT_ + nf * 8) =
            make_float2(rnd_tf32(o[nf][2] * inv1), rnd_tf32(o[nf][3] * inv1));
    }
}

// ---------------------------------------------------------------------------
extern "C" void kernel_launch(void* const* d_in, const int* in_sizes, int n_in,
                              void* d_out, int out_size) {
    const float* x    = (const float*)d_in[0];
    const float* cosp = (const float*)d_in[1];
    const float* sinp = (const float*)d_in[2];
    const float* wq   = (const float*)d_in[3];
    const float* wk   = (const float*)d_in[4];
    const float* wv   = (const float*)d_in[5];
    const float* wo   = (const float*)d_in[6];
    const float* qw   = (const float*)d_in[7];
    const float* kw   = (const float*)d_in[8];
    float* out = (float*)d_out;

    float *xr, *wt, *wot, *QKV, *A;
    cudaGetSymbolAddress((void**)&xr,  g_xr);
    cudaGetSymbolAddress((void**)&wt,  g_wt);
    cudaGetSymbolAddress((void**)&wot, g_wot);
    cudaGetSymbolAddress((void**)&QKV, g_QKV);
    cudaGetSymbolAddress((void**)&A,   g_A);

    const int smem_sz = NSTG_ * STG_F_ * 4;   // 110592 B
    cudaFuncSetAttribute(gemm_tf32, cudaFuncAttributeMaxDynamicSharedMemorySize, smem_sz);
    const int fa_smem = FA_SMF * 4;           // 70656 B
    cudaFuncSetAttribute(flash_mma, cudaFuncAttributeMaxDynamicSharedMemorySize, fa_smem);

    // Prep: round x; transpose+round weights
    cvt_round4<<<(SEQ_ * DIN_ / 4 + 255) / 256, 256>>>(x, xr, SEQ_ * DIN_ / 4);
    tposer3<<<dim3(64, DIN_ / 32, 3), dim3(32, 8)>>>(wq, wk, wv, wt);
    tposer<<<dim3(2048 / 32, DOUT_ / 32), dim3(32, 8)>>>(wo, 2048, wot, 0);

    // Fused QKV projection (tf32 tensor cores, warp-64x64 config)
    gemm_tf32<<<dim3(DQKV_ / 128, SEQ_ / 128), 128, smem_sz>>>(xr, wt, QKV, DQKV_);

    // RMSNorm + RoPE (K rounded to tf32 in-pass); round V region
    norm_rope<<<(SEQ_ * NH_ * 32) / 256, 256>>>(QKV, qw, cosp, sinp, NH_, DQKV_, 0);
    norm_rope<<<(SEQ_ * NKV_ * 32) / 256, 256>>>(QKV + 2048, kw, cosp, sinp, NKV_, DQKV_, 1);
    round_v<<<SEQ_ * 128 / 256, 256>>>();

    // Tensor-core causal GQA attention
    flash_mma<<<dim3(SEQ_ / 128, NH_), 256, fa_smem>>>();

    // Output projection (tf32 tensor cores)
    gemm_tf32<<<dim3(DIN_ / 128, SEQ_ / 128), 128, smem_sz>>>(A, wot, out, DIN_);
}

// round 11
// speedup vs baseline: 1.1215x; 1.1003x over previous
#include <cuda_runtime.h>
#include <cuda_fp16.h>
#include <cstdint>
#include <math.h>

#define SEQ_    2048
#define DIN_    2048
#define NH_     32
#define NKV_    8
#define HD_     64
#define DQKV_   3072            // Q(2048) | K(512) | V(512) fused columns
#define DOUT_   2048
#define GK_     2048            // GEMM K (both GEMMs have K=2048)

// ---------------------------------------------------------------------------
// Scratch (__device__ globals; allocation-free rule)
// ---------------------------------------------------------------------------
__device__ __half g_xh[SEQ_ * DIN_];       // x in fp16
__device__ __half g_wth[DQKV_ * DIN_];     // W_qkv^T [3072][2048] fp16
__device__ __half g_woth[DIN_ * DOUT_];    // Wo^T    [2048][2048] fp16
__device__ float  g_QKV[SEQ_ * DQKV_];     // fp32 GEMM out: Q | K | V
__device__ __half g_Kh[SEQ_ * 512];        // normed+roped K, fp16 [seq][kvh*64]
__device__ __half g_Vth[NKV_ * HD_ * SEQ_];// V transposed fp16 [kvh][dim][seq]
__device__ __half g_Ah[SEQ_ * DOUT_];      // attention out fp16

// ---------------------------------------------------------------------------
// Helpers (baseline PTX only)
// ---------------------------------------------------------------------------
__device__ __forceinline__ uint32_t smem_u32(const void* p) {
    uint32_t a;
    asm("{ .reg .u64 t; cvta.to.shared.u64 t, %1; cvt.u32.u64 %0, t; }" : "=r"(a) : "l"(p));
    return a;
}
__device__ __forceinline__ void cpasync16(uint32_t dst, const void* src) {
    asm volatile("cp.async.cg.shared.global [%0], [%1], 16;" :: "r"(dst), "l"(src));
}
#define CP_COMMIT()  asm volatile("cp.async.commit_group;" ::: "memory")
#define CP_WAIT(n)   asm volatile("cp.async.wait_group %0;" :: "n"(n) : "memory")

// fp16 mma: D(f32) += A(f16) * B(f16), m16n8k16
__device__ __forceinline__ void mma_f16(float* d, const uint32_t* a, const uint32_t* b) {
    asm volatile(
        "mma.sync.aligned.m16n8k16.row.col.f32.f16.f16.f32 "
        "{%0,%1,%2,%3}, {%4,%5,%6,%7}, {%8,%9}, {%0,%1,%2,%3};"
        : "+f"(d[0]), "+f"(d[1]), "+f"(d[2]), "+f"(d[3])
        : "r"(a[0]), "r"(a[1]), "r"(a[2]), "r"(a[3]), "r"(b[0]), "r"(b[1]));
}
__device__ __forceinline__ uint32_t packh2(float x, float y) {
    __half2 h = __floats2half2_rn(x, y);
    return *(uint32_t*)&h;
}

// ---------------------------------------------------------------------------
// Prep kernels
// ---------------------------------------------------------------------------
__global__ void cvt_h(const float* __restrict__ src, __half* __restrict__ dst, int n2) {
    int i = blockIdx.x * blockDim.x + threadIdx.x;
    if (i >= n2) return;
    float2 v = ((const float2*)src)[i];
    ((uint32_t*)dst)[i] = packh2(v.x, v.y);
}

// Transpose + fp16: W[K=2048, ncols] -> out[(row_off+n)*2048 + k]
__device__ __forceinline__ void tpose_body(const float* __restrict__ W, int ncols,
                                           __half* __restrict__ out, int row_off,
                                           int bx, int by) {
    __shared__ float t[32][33];
    int tx = threadIdx.x, ty = threadIdx.y;
    int x = bx * 32 + tx;
    int y = by * 32 + ty;
#pragma unroll
    for (int i = 0; i < 32; i += 8)
        t[ty + i][tx] = W[(size_t)(y + i) * ncols + x];
    __syncthreads();
    int n = bx * 32 + ty;
    int k = by * 32 + tx;
#pragma unroll
    for (int i = 0; i < 32; i += 8)
        out[(size_t)(row_off + n + i) * GK_ + k] = __float2half_rn(t[tx][ty + i]);
}

__global__ void tposer(const float* __restrict__ W, int ncols,
                       __half* __restrict__ out, int row_off) {
    tpose_body(W, ncols, out, row_off, blockIdx.x, blockIdx.y);
}

__global__ void tposer3(const float* __restrict__ wq, const float* __restrict__ wk,
                        const float* __restrict__ wv, __half* __restrict__ out) {
    int z = blockIdx.z;
    if (z == 0) {
        tpose_body(wq, 2048, out, 0, blockIdx.x, blockIdx.y);
    } else if (z == 1) {
        if (blockIdx.x < 16) tpose_body(wk, 512, out, 2048, blockIdx.x, blockIdx.y);
    } else {
        if (blockIdx.x < 16) tpose_body(wv, 512, out, 2560, blockIdx.x, blockIdx.y);
    }
}

// Transpose V region of g_QKV (cols 2560..3071) -> g_Vth[kvh][dim][seq] fp16
__global__ void vtpose() {
    __shared__ float t[32][33];
    int tx = threadIdx.x, ty = threadIdx.y;
    int kvh = blockIdx.z;
    int dim0 = blockIdx.x * 32;
    int seq0 = blockIdx.y * 32;
#pragma unroll
    for (int i = 0; i < 32; i += 8)
        t[ty + i][tx] = g_QKV[(size_t)(seq0 + ty + i) * DQKV_ + 2560 + kvh * HD_ + dim0 + tx];
    __syncthreads();
#pragma unroll
    for (int i = 0; i < 32; i += 8)
        g_Vth[(size_t)kvh * HD_ * SEQ_ + (size_t)(dim0 + ty + i) * SEQ_ + seq0 + tx] =
            __float2half_rn(t[tx][ty + i]);
}

// ---------------------------------------------------------------------------
// Fused RMSNorm + RoPE. Q pass: fp32 in place. K pass: fp16 out to g_Kh.
// ---------------------------------------------------------------------------
__global__ void norm_rope(float* __restrict__ X, const float* __restrict__ w,
                          const float* __restrict__ cosp, const float* __restrict__ sinp,
                          int nheads, int rowdim, __half* __restrict__ hout) {
    int gwarp = (blockIdx.x * blockDim.x + threadIdx.x) >> 5;
    int lane = threadIdx.x & 31;
    int s = gwarp / nheads;
    int h = gwarp % nheads;
    if (s >= SEQ_) return;

    float* p = X + (size_t)s * rowdim + h * HD_;
    float x0 = p[lane];
    float x1 = p[lane + 32];

    float ss = x0 * x0 + x1 * x1;
#pragma unroll
    for (int off = 16; off; off >>= 1) ss += __shfl_xor_sync(0xFFFFFFFFu, ss, off);
    float r = rsqrtf(ss * (1.f / 64.f) + 1e-6f);

    x0 = x0 * r * w[lane];
    x1 = x1 * r * w[lane + 32];

    float c0 = cosp[s * HD_ + lane],      s0 = sinp[s * HD_ + lane];
    float c1 = cosp[s * HD_ + lane + 32], s1 = sinp[s * HD_ + lane + 32];

    float y0 = x0 * c0 - x1 * s0;
    float y1 = x1 * c1 + x0 * s1;
    if (hout) {
        __half* q = hout + (size_t)s * 512 + h * HD_;
        q[lane]      = __float2half_rn(y0);
        q[lane + 32] = __float2half_rn(y1);
    } else {
        p[lane]      = y0;
        p[lane + 32] = y1;
    }
}

// ---------------------------------------------------------------------------
// fp16 mma.sync GEMM: C[M,N](f32) = A[M,2048] @ Bt[N,2048]^T (A,Bt fp16).
// CTA tile 128x128, BK=32, 4 warps (2x2, warp tile 64x64), 3-stage cp.async.
// smem rows: 32 halves data + 8 pad = 20 words (80 B) -> conflict-free frags.
// ---------------------------------------------------------------------------
#define NCHG_   (GK_ / 32)      // 64
#define GW_     20              // words per smem row
#define GTILE_W (128 * GW_)     // 2560 words per tile
#define GSTG_W  (2 * GTILE_W)   // 5120 words per stage
#define GNSTG_  3

__global__ __launch_bounds__(128, 2) void gemm_f16(
    const __half* __restrict__ A, const __half* __restrict__ Bt,
    float* __restrict__ C, int ldc)
{
    extern __shared__ uint32_t smw[];
    const int tid = threadIdx.x;
    const int w = tid >> 5, lane = tid & 31;
    const int bm = blockIdx.y * 128, bn = blockIdx.x * 128;
    const int warp_m = (w & 1) * 64, warp_n = (w >> 1) * 64;
    const int tr = lane >> 2, tc = lane & 3;

    float acc[4][8][4];
#pragma unroll
    for (int i = 0; i < 4; i++)
#pragma unroll
        for (int j = 0; j < 8; j++)
#pragma unroll
            for (int r = 0; r < 4; r++) acc[i][j][r] = 0.f;

    const __half* Ag = A + (size_t)bm * GK_;
    const __half* Bg = Bt + (size_t)bn * GK_;
    const int lrow = tid >> 2;              // 0..31, rows via +=32
    const int lq = tid & 3;                 // 16B chunk within 64B row
    uint32_t sbase = smem_u32(smw);

    auto issue = [&](int c) {
        uint32_t sA = sbase + (uint32_t)(c % GNSTG_) * GSTG_W * 4;
        uint32_t sB = sA + GTILE_W * 4;
        const int k0 = c * 32;
#pragma unroll
        for (int i = 0; i < 4; i++) {
            int row = lrow + i * 32;
            uint32_t off = (uint32_t)(row * GW_ + lq * 4) * 4;
            cpasync16(sA + off, Ag + (size_t)row * GK_ + k0 + lq * 8);
            cpasync16(sB + off, Bg + (size_t)row * GK_ + k0 + lq * 8);
        }
        CP_COMMIT();
    };

    issue(0);
    issue(1);

    for (int c = 0; c < NCHG_; c++) {
        if (c + 1 < NCHG_) CP_WAIT(1); else CP_WAIT(0);
        __syncthreads();
        if (c + 2 < NCHG_) issue(c + 2);

        const uint32_t* As = smw + (c % GNSTG_) * GSTG_W;
        const uint32_t* Bs = As + GTILE_W;

#pragma unroll
        for (int kk = 0; kk < 2; kk++) {
            const int kb = kk * 8;
            uint32_t a[4][4], b[8][2];
#pragma unroll
            for (int mt = 0; mt < 4; mt++) {
                const uint32_t* ap = As + (warp_m + mt * 16 + tr) * GW_ + kb + tc;
                a[mt][0] = ap[0];
                a[mt][1] = ap[8 * GW_];
                a[mt][2] = ap[4];
                a[mt][3] = ap[8 * GW_ + 4];
            }
#pragma unroll
            for (int nt = 0; nt < 8; nt++) {
                const uint32_t* bp = Bs + (warp_n + nt * 8 + tr) * GW_ + kb + tc;
                b[nt][0] = bp[0];
                b[nt][1] = bp[4];
            }
#pragma unroll
            for (int mt = 0; mt < 4; mt++)
#pragma unroll
                for (int nt = 0; nt < 8; nt++)
                    mma_f16(acc[mt][nt], a[mt], b[nt]);
        }
    }

#pragma unroll
    for (int mt = 0; mt < 4; mt++)
#pragma unroll
        for (int nt = 0; nt < 8; nt++) {
            int row = bm + warp_m + mt * 16 + tr;
            int col = bn + warp_n + nt * 8 + 2 * tc;
            *(float2*)(C + (size_t)row * ldc + col) =
                make_float2(acc[mt][nt][0], acc[mt][nt][1]);
            *(float2*)(C + (size_t)(row + 8) * ldc + col) =
                make_float2(acc[mt][nt][2], acc[mt][nt][3]);
        }
}

// ---------------------------------------------------------------------------
// fp16 tensor-core causal GQA flash attention.
// CTA = (q-block 128, head). 8 warps x 16 q-rows. P stays in registers
// (fp16 C-frag == A-frag layout when packed to half2).
// smem: Qs fp32 [128][68] | K fp16 [2][32 keys][144B] | Vt fp16 [2][64 dims][80B]
// ---------------------------------------------------------------------------
#define QS_ST   68
#define KW_     36              // words per K row (64 halves + pad)
#define VW_     20              // words per Vt row (32 halves + pad)
#define KS_OFFW (128 * QS_ST)               // word offset of K buffers
#define VS_OFFW (KS_OFFW + 2 * 32 * KW_)
#define FA_SMW  (VS_OFFW + 2 * 64 * VW_)    // total words = 13568 -> 54272 B

__global__ __launch_bounds__(256, 2) void flash_f16() {
    extern __shared__ uint32_t smw[];
    float* Qs = (float*)smw;
    const int tid = threadIdx.x;
    const int w = tid >> 5, lane = tid & 31;
    const int tr = lane >> 2, tc = lane & 3;
    const int h = blockIdx.y;
    const int q0 = blockIdx.x * 128;
    const int kvh = h >> 2;
    const uint32_t sb = smem_u32(smw);

    const __half* Kg = g_Kh + kvh * HD_;
    const __half* Vg = g_Vth + (size_t)kvh * HD_ * SEQ_;

    // prefetch tile 0 (K: 32 rows x 128B; Vt: 64 rows x 64B)
    {
        int kr = tid >> 3, kq = tid & 7;
        cpasync16(sb + (KS_OFFW + kr * KW_ + kq * 4) * 4,
                  Kg + (size_t)kr * 512 + kq * 8);
        int vr = tid >> 2, vq = tid & 3;
        cpasync16(sb + (VS_OFFW + vr * VW_ + vq * 4) * 4,
                  Vg + (size_t)vr * SEQ_ + vq * 8);
        CP_COMMIT();
    }

    // stage Q (fp32) and build fp16 A-fragments
    {
        const float* Qgp = g_QKV + (size_t)q0 * DQKV_ + h * HD_;
#pragma unroll
        for (int i = 0; i < 8; i++) {
            int idx = tid + i * 256;
            int row = idx >> 4, c4 = idx & 15;
            *(float4*)&Qs[row * QS_ST + c4 * 4] =
                *(const float4*)(Qgp + (size_t)row * DQKV_ + c4 * 4);
        }
    }
    __syncthreads();

    uint32_t q[4][4];
    {
        const float scale = 0.125f;
        const float* q0p = Qs + (w * 16 + tr) * QS_ST;
        const float* q1p = q0p + 8 * QS_ST;
#pragma unroll
        for (int kk = 0; kk < 4; kk++) {
            int c = 16 * kk + 2 * tc;
            q[kk][0] = packh2(q0p[c] * scale, q0p[c + 1] * scale);
            q[kk][1] = packh2(q1p[c] * scale, q1p[c + 1] * scale);
            q[kk][2] = packh2(q0p[c + 8] * scale, q0p[c + 9] * scale);
            q[kk][3] = packh2(q1p[c + 8] * scale, q1p[c + 9] * scale);
        }
    }

    float o[8][4];
#pragma unroll
    for (int nf = 0; nf < 8; nf++)
#pragma unroll
        for (int r = 0; r < 4; r++) o[nf][r] = 0.f;
    float m0 = -1e30f, m1 = -1e30f, l0 = 0.f, l1 = 0.f;

    const int ntiles = (q0 + 128) / 32;

    for (int t = 0; t < ntiles; t++) {
        const int k0 = t * 32;
        if (t + 1 < ntiles) {
            const int kn = (t + 1) * 32;
            const int buf = (t + 1) & 1;
            int kr = tid >> 3, kq = tid & 7;
            cpasync16(sb + (KS_OFFW + (buf * 32 + kr) * KW_ + kq * 4) * 4,
                      Kg + (size_t)(kn + kr) * 512 + kq * 8);
            int vr = tid >> 2, vq = tid & 3;
            cpasync16(sb + (VS_OFFW + (buf * 64 + vr) * VW_ + vq * 4) * 4,
                      Vg + (size_t)vr * SEQ_ + kn + vq * 8);
            CP_COMMIT();
            CP_WAIT(1);
        } else {
            CP_WAIT(0);
        }
        __syncthreads();

        if (k0 <= q0 + w * 16 + 15) {
            const uint32_t* Kt = smw + KS_OFFW + (t & 1) * 32 * KW_;
            const uint32_t* Vt = smw + VS_OFFW + (t & 1) * 64 * VW_;

            // ---- scores S[16][32] = Q @ K^T (k = 64 dims, 4 k16 steps) ----
            float s[4][4];
#pragma unroll
            for (int nf = 0; nf < 4; nf++) {
                s[nf][0] = s[nf][1] = s[nf][2] = s[nf][3] = 0.f;
                const uint32_t* bp = Kt + (nf * 8 + tr) * KW_ + tc;
#pragma unroll
                for (int kk = 0; kk < 4; kk++) {
                    uint32_t b[2] = { bp[kk * 8], bp[kk * 8 + 4] };
                    mma_f16(s[nf], q[kk], b);
                }
            }

            // ---- causal mask ----
            if (k0 + 31 > q0 + w * 16) {
                const int r0 = q0 + w * 16 + tr, r1 = r0 + 8;
                const int cb = k0 + 2 * tc;
#pragma unroll
                for (int nf = 0; nf < 4; nf++) {
                    int c0 = cb + nf * 8, c1 = c0 + 1;
                    if (c0 > r0) s[nf][0] = -1e30f;
                    if (c1 > r0) s[nf][1] = -1e30f;
                    if (c0 > r1) s[nf][2] = -1e30f;
                    if (c1 > r1) s[nf][3] = -1e30f;
                }
            }

            // ---- online softmax (rows tr -> m0/l0, rows tr+8 -> m1/l1) ----
            float t0 = fmaxf(fmaxf(s[0][0], s[0][1]), fmaxf(s[1][0], s[1][1]));
            t0 = fmaxf(t0, fmaxf(fmaxf(s[2][0], s[2][1]), fmaxf(s[3][0], s[3][1])));
            float t1 = fmaxf(fmaxf(s[0][2], s[0][3]), fmaxf(s[1][2], s[1][3]));
            t1 = fmaxf(t1, fmaxf(fmaxf(s[2][2], s[2][3]), fmaxf(s[3][2], s[3][3])));
            t0 = fmaxf(t0, __shfl_xor_sync(0xFFFFFFFFu, t0, 1));
            t0 = fmaxf(t0, __shfl_xor_sync(0xFFFFFFFFu, t0, 2));
            t1 = fmaxf(t1, __shfl_xor_sync(0xFFFFFFFFu, t1, 1));
            t1 = fmaxf(t1, __shfl_xor_sync(0xFFFFFFFFu, t1, 2));
            const float mt0 = fmaxf(m0, t0), mt1 = fmaxf(m1, t1);
            const float corr0 = __expf(m0 - mt0), corr1 = __expf(m1 - mt1);
            m0 = mt0; m1 = mt1;

            float pv[4][4];           // exp'd scores, fp32
            float sum0 = 0.f, sum1 = 0.f;
#pragma unroll
            for (int nf = 0; nf < 4; nf++) {
                pv[nf][0] = __expf(s[nf][0] - mt0);
                pv[nf][1] = __expf(s[nf][1] - mt0);
                pv[nf][2] = __expf(s[nf][2] - mt1);
                pv[nf][3] = __expf(s[nf][3] - mt1);
                sum0 += pv[nf][0] + pv[nf][1];
                sum1 += pv[nf][2] + pv[nf][3];
            }
            sum0 += __shfl_xor_sync(0xFFFFFFFFu, sum0, 1);
            sum0 += __shfl_xor_sync(0xFFFFFFFFu, sum0, 2);
            sum1 += __shfl_xor_sync(0xFFFFFFFFu, sum1, 1);
            sum1 += __shfl_xor_sync(0xFFFFFFFFu, sum1, 2);
            l0 = l0 * corr0 + sum0;
            l1 = l1 * corr1 + sum1;

#pragma unroll
            for (int nf = 0; nf < 8; nf++) {
                o[nf][0] *= corr0; o[nf][1] *= corr0;
                o[nf][2] *= corr1; o[nf][3] *= corr1;
            }

            // ---- O += P @ V, P packed reg->reg (C-frag == A-frag layout) ----
#pragma unroll
            for (int kkp = 0; kkp < 2; kkp++) {
                uint32_t a[4] = {
                    packh2(pv[2 * kkp][0],     pv[2 * kkp][1]),
                    packh2(pv[2 * kkp][2],     pv[2 * kkp][3]),
                    packh2(pv[2 * kkp + 1][0], pv[2 * kkp + 1][1]),
                    packh2(pv[2 * kkp + 1][2], pv[2 * kkp + 1][3])
                };
#pragma unroll
                for (int nt = 0; nt < 8; nt++) {
                    const uint32_t* vp = Vt + (nt * 8 + tr) * VW_ + kkp * 8 + tc;
                    uint32_t b[2] = { vp[0], vp[4] };
                    mma_f16(o[nt], a, b);
                }
            }
        }
        __syncthreads();
    }

    // ---- epilogue: write fp16 attention output ----
    const float inv0 = 1.f / l0, inv1 = 1.f / l1;
    const int r0 = q0 + w * 16 + tr;
    uint32_t* Og = (uint32_t*)(g_Ah + (size_t)r0 * DOUT_ + h * HD_ + 2 * tc);
    uint32_t* Og8 = (uint32_t*)(g_Ah + (size_t)(r0 + 8) * DOUT_ + h * HD_ + 2 * tc);
#pragma unroll
    for (int nf = 0; nf < 8; nf++) {
        Og[nf * 4]  = packh2(o[nf][0] * inv0, o[nf][1] * inv0);
        Og8[nf * 4] = packh2(o[nf][2] * inv1, o[nf][3] * inv1);
    }
}

// ---------------------------------------------------------------------------
extern "C" void kernel_launch(void* const* d_in, const int* in_sizes, int n_in,
                              void* d_out, int out_size) {
    const float* x    = (const float*)d_in[0];
    const float* cosp = (const float*)d_in[1];
    const float* sinp = (const float*)d_in[2];
    const float* wq   = (const float*)d_in[3];
    const float* wk   = (const float*)d_in[4];
    const float* wv   = (const float*)d_in[5];
    const float* wo   = (const float*)d_in[6];
    const float* qw   = (const float*)d_in[7];
    const float* kw   = (const float*)d_in[8];
    float* out = (float*)d_out;

    float *QKV;
    __half *xh, *wth, *woth, *Kh, *Ah;
    cudaGetSymbolAddress((void**)&xh,   g_xh);
    cudaGetSymbolAddress((void**)&wth,  g_wth);
    cudaGetSymbolAddress((void**)&woth, g_woth);
    cudaGetSymbolAddress((void**)&QKV,  g_QKV);
    cudaGetSymbolAddress((void**)&Kh,   g_Kh);
    cudaGetSymbolAddress((void**)&Ah,   g_Ah);

    const int gsmem = GNSTG_ * GSTG_W * 4;    // 61440 B
    cudaFuncSetAttribute(gemm_f16, cudaFuncAttributeMaxDynamicSharedMemorySize, gsmem);
    const int fsmem = FA_SMW * 4;             // 54272 B
    cudaFuncSetAttribute(flash_f16, cudaFuncAttributeMaxDynamicSharedMemorySize, fsmem);

    // Prep: x -> fp16; weights transpose -> fp16
    cvt_h<<<(SEQ_ * DIN_ / 2 + 255) / 256, 256>>>(x, xh, SEQ_ * DIN_ / 2);
    tposer3<<<dim3(64, DIN_ / 32, 3), dim3(32, 8)>>>(wq, wk, wv, wth);
    tposer<<<dim3(2048 / 32, DOUT_ / 32), dim3(32, 8)>>>(wo, 2048, woth, 0);

    // Fused QKV projection (fp16 tensor cores, fp32 out)
    gemm_f16<<<dim3(DQKV_ / 128, SEQ_ / 128), 128, gsmem>>>(xh, wth, QKV, DQKV_);

    // RMSNorm + RoPE: Q in place fp32; K -> fp16 g_Kh. V -> transposed fp16.
    norm_rope<<<(SEQ_ * NH_ * 32) / 256, 256>>>(QKV, qw, cosp, sinp, NH_, DQKV_, (half*)0);
    norm_rope<<<(SEQ_ * NKV_ * 32) / 256, 256>>>(QKV + 2048, kw, cosp, sinp, NKV_, DQKV_, Kh);
    vtpose<<<dim3(HD_ / 32, SEQ_ / 32, NKV_), dim3(32, 8)>>>();

    // Tensor-core causal GQA attention (fp16), writes fp16 g_Ah
    flash_f16<<<dim3(SEQ_ / 128, NH_), 256, fsmem>>>();

    // Output projection (fp16 tensor cores, fp32 out)
    gemm_f16<<<dim3(DIN_ / 128, SEQ_ / 128), 128, gsmem>>>(Ah, woth, out, DIN_);
}

// round 13
// speedup vs baseline: 1.5967x; 1.4236x over previous
#include <cuda_runtime.h>
#include <cuda_fp16.h>
#include <cstdint>
#include <math.h>

#define SEQ_    2048
#define DIN_    2048
#define NH_     32
#define NKV_    8
#define HD_     64
#define DQKV_   3072            // Q(2048) | K(512) | V(512) fused columns
#define DOUT_   2048
#define GK_     2048            // GEMM K (both GEMMs have K=2048)

// ---------------------------------------------------------------------------
// Scratch (__device__ globals; allocation-free rule)
// ---------------------------------------------------------------------------
__device__ __half g_xh[SEQ_ * DIN_];       // x in fp16
__device__ __half g_wth[DQKV_ * DIN_];     // W_qkv^T [3072][2048] fp16
__device__ __half g_woth[DIN_ * DOUT_];    // Wo^T    [2048][2048] fp16
__device__ float  g_QKV[SEQ_ * DQKV_];     // fp32 GEMM out: Q | K | V
__device__ __half g_Kh[SEQ_ * 512];        // normed+roped K, fp16 [seq][kvh*64]
__device__ __half g_Vth[NKV_ * HD_ * SEQ_];// V transposed fp16 [kvh][dim][seq]
__device__ __half g_Ah[SEQ_ * DOUT_];      // attention out fp16

// ---------------------------------------------------------------------------
// Helpers (baseline PTX only)
// ---------------------------------------------------------------------------
__device__ __forceinline__ uint32_t smem_u32(const void* p) {
    uint32_t a;
    asm("{ .reg .u64 t; cvta.to.shared.u64 t, %1; cvt.u32.u64 %0, t; }" : "=r"(a) : "l"(p));
    return a;
}
__device__ __forceinline__ void cpasync16(uint32_t dst, const void* src) {
    asm volatile("cp.async.cg.shared.global [%0], [%1], 16;" :: "r"(dst), "l"(src));
}
#define CP_COMMIT()  asm volatile("cp.async.commit_group;" ::: "memory")
#define CP_WAIT(n)   asm volatile("cp.async.wait_group %0;" :: "n"(n) : "memory")

// fp16 mma: D(f32) += A(f16) * B(f16), m16n8k16
__device__ __forceinline__ void mma_f16(float* d, const uint32_t* a, const uint32_t* b) {
    asm volatile(
        "mma.sync.aligned.m16n8k16.row.col.f32.f16.f16.f32 "
        "{%0,%1,%2,%3}, {%4,%5,%6,%7}, {%8,%9}, {%0,%1,%2,%3};"
        : "+f"(d[0]), "+f"(d[1]), "+f"(d[2]), "+f"(d[3])
        : "r"(a[0]), "r"(a[1]), "r"(a[2]), "r"(a[3]), "r"(b[0]), "r"(b[1]));
}
__device__ __forceinline__ uint32_t packh2(float x, float y) {
    __half2 h = __floats2half2_rn(x, y);
    return *(uint32_t*)&h;
}

// ---------------------------------------------------------------------------
// Prep kernels
// ---------------------------------------------------------------------------
__global__ void cvt_h(const float* __restrict__ src, __half* __restrict__ dst, int n2) {
    int i = blockIdx.x * blockDim.x + threadIdx.x;
    if (i >= n2) return;
    float2 v = ((const float2*)src)[i];
    ((uint32_t*)dst)[i] = packh2(v.x, v.y);
}

// Transpose + fp16: W[K=2048, ncols] -> out[(row_off+n)*2048 + k]
__device__ __forceinline__ void tpose_body(const float* __restrict__ W, int ncols,
                                           __half* __restrict__ out, int row_off,
                                           int bx, int by) {
    __shared__ float t[32][33];
    int tx = threadIdx.x, ty = threadIdx.y;
    int x = bx * 32 + tx;
    int y = by * 32 + ty;
#pragma unroll
    for (int i = 0; i < 32; i += 8)
        t[ty + i][tx] = W[(size_t)(y + i) * ncols + x];
    __syncthreads();
    int n = bx * 32 + ty;
    int k = by * 32 + tx;
#pragma unroll
    for (int i = 0; i < 32; i += 8)
        out[(size_t)(row_off + n + i) * GK_ + k] = __float2half_rn(t[tx][ty + i]);
}

__global__ void tposer(const float* __restrict__ W, int ncols,
                       __half* __restrict__ out, int row_off) {
    tpose_body(W, ncols, out, row_off, blockIdx.x, blockIdx.y);
}

__global__ void tposer3(const float* __restrict__ wq, const float* __restrict__ wk,
                        const float* __restrict__ wv, __half* __restrict__ out) {
    int z = blockIdx.z;
    if (z == 0) {
        tpose_body(wq, 2048, out, 0, blockIdx.x, blockIdx.y);
    } else if (z == 1) {
        if (blockIdx.x < 16) tpose_body(wk, 512, out, 2048, blockIdx.x, blockIdx.y);
    } else {
        if (blockIdx.x < 16) tpose_body(wv, 512, out, 2560, blockIdx.x, blockIdx.y);
    }
}

// Transpose V region of g_QKV (cols 2560..3071) -> g_Vth[kvh][dim][seq] fp16
__global__ void vtpose() {
    __shared__ float t[32][33];
    int tx = threadIdx.x, ty = threadIdx.y;
    int kvh = blockIdx.z;
    int dim0 = blockIdx.x * 32;
    int seq0 = blockIdx.y * 32;
#pragma unroll
    for (int i = 0; i < 32; i += 8)
        t[ty + i][tx] = g_QKV[(size_t)(seq0 + ty + i) * DQKV_ + 2560 + kvh * HD_ + dim0 + tx];
    __syncthreads();
#pragma unroll
    for (int i = 0; i < 32; i += 8)
        g_Vth[(size_t)kvh * HD_ * SEQ_ + (size_t)(dim0 + ty + i) * SEQ_ + seq0 + tx] =
            __float2half_rn(t[tx][ty + i]);
}

// ---------------------------------------------------------------------------
// Fused RMSNorm + RoPE. Q pass: fp32 in place. K pass: fp16 out to g_Kh.
// ---------------------------------------------------------------------------
__global__ void norm_rope(float* __restrict__ X, const float* __restrict__ w,
                          const float* __restrict__ cosp, const float* __restrict__ sinp,
                          int nheads, int rowdim, __half* __restrict__ hout) {
    int gwarp = (blockIdx.x * blockDim.x + threadIdx.x) >> 5;
    int lane = threadIdx.x & 31;
    int s = gwarp / nheads;
    int h = gwarp % nheads;
    if (s >= SEQ_) return;

    float* p = X + (size_t)s * rowdim + h * HD_;
    float x0 = p[lane];
    float x1 = p[lane + 32];

    float ss = x0 * x0 + x1 * x1;
#pragma unroll
    for (int off = 16; off; off >>= 1) ss += __shfl_xor_sync(0xFFFFFFFFu, ss, off);
    float r = rsqrtf(ss * (1.f / 64.f) + 1e-6f);

    x0 = x0 * r * w[lane];
    x1 = x1 * r * w[lane + 32];

    float c0 = cosp[s * HD_ + lane],      s0 = sinp[s * HD_ + lane];
    float c1 = cosp[s * HD_ + lane + 32], s1 = sinp[s * HD_ + lane + 32];

    float y0 = x0 * c0 - x1 * s0;
    float y1 = x1 * c1 + x0 * s1;
    if (hout) {
        __half* q = hout + (size_t)s * 512 + h * HD_;
        q[lane]      = __float2half_rn(y0);
        q[lane + 32] = __float2half_rn(y1);
    } else {
        p[lane]      = y0;
        p[lane + 32] = y1;
    }
}

// ---------------------------------------------------------------------------
// fp16 mma.sync GEMM: C[M,N](f32) = A[M,2048] @ Bt[N,2048]^T (A,Bt fp16).
// CTA tile 64x128, BK=32, 4 warps (2x2, warp tile 32x64), 128 threads,
// 4-stage cp.async, 3 CTAs/SM target. Row stride 20 words -> conflict-free.
// ---------------------------------------------------------------------------
#define NCHG_   (GK_ / 32)      // 64
#define GW_     20              // words per smem row (32 halves + pad)
#define AROWS_  64
#define SROWS_  192             // 64 A rows + 128 B rows
#define SSTG_W  (SROWS_ * GW_)  // 3840 words per stage
#define GNSTG_  4

__global__ __launch_bounds__(128, 3) void gemm_f16(
    const __half* __restrict__ A, const __half* __restrict__ Bt,
    float* __restrict__ C, int ldc)
{
    extern __shared__ uint32_t smw[];
    const int tid = threadIdx.x;
    const int w = tid >> 5, lane = tid & 31;
    const int bm = blockIdx.y * 64, bn = blockIdx.x * 128;
    const int warp_m = (w & 1) * 32, warp_n = (w >> 1) * 64;
    const int tr = lane >> 2, tc = lane & 3;

    float acc[2][8][4];
#pragma unroll
    for (int i = 0; i < 2; i++)
#pragma unroll
        for (int j = 0; j < 8; j++)
#pragma unroll
            for (int r = 0; r < 4; r++) acc[i][j][r] = 0.f;

    const __half* Ag = A + (size_t)bm * GK_;
    const __half* Bg = Bt + (size_t)bn * GK_;
    const int lrow = tid >> 2;              // 0..31
    const int lq = tid & 3;                 // 16B chunk within 64B row
    uint32_t sbase = smem_u32(smw);

    auto issue = [&](int c) {
        uint32_t sA = sbase + (uint32_t)(c & 3) * SSTG_W * 4;
        uint32_t sB = sA + AROWS_ * GW_ * 4;
        const int k0 = c * 32;
#pragma unroll
        for (int i = 0; i < 2; i++) {       // A: 64 rows
            int row = lrow + i * 32;
            cpasync16(sA + (uint32_t)(row * GW_ + lq * 4) * 4,
                      Ag + (size_t)row * GK_ + k0 + lq * 8);
        }
#pragma unroll
        for (int i = 0; i < 4; i++) {       // B: 128 rows
            int row = lrow + i * 32;
            cpasync16(sB + (uint32_t)(row * GW_ + lq * 4) * 4,
                      Bg + (size_t)row * GK_ + k0 + lq * 8);
        }
        CP_COMMIT();
    };

    issue(0); issue(1); issue(2);

    for (int c = 0; c < NCHG_; c++) {
        const int rem = NCHG_ - 1 - c;
        if (rem >= 2) CP_WAIT(2);
        else if (rem == 1) CP_WAIT(1);
        else CP_WAIT(0);
        __syncthreads();
        if (c + 3 < NCHG_) issue(c + 3);    // stage (c+3)&3 == (c-1)&3: done by barrier

        const uint32_t* As = smw + (c & 3) * SSTG_W;
        const uint32_t* Bs = As + AROWS_ * GW_;

#pragma unroll
        for (int kk = 0; kk < 2; kk++) {
            const int kb = kk * 8;
            uint32_t a[2][4], b[8][2];
#pragma unroll
            for (int mt = 0; mt < 2; mt++) {
                const uint32_t* ap = As + (warp_m + mt * 16 + tr) * GW_ + kb + tc;
                a[mt][0] = ap[0];
                a[mt][1] = ap[8 * GW_];
                a[mt][2] = ap[4];
                a[mt][3] = ap[8 * GW_ + 4];
            }
#pragma unroll
            for (int nt = 0; nt < 8; nt++) {
                const uint32_t* bp = Bs + (warp_n + nt * 8 + tr) * GW_ + kb + tc;
                b[nt][0] = bp[0];
                b[nt][1] = bp[4];
            }
#pragma unroll
            for (int mt = 0; mt < 2; mt++)
#pragma unroll
                for (int nt = 0; nt < 8; nt++)
                    mma_f16(acc[mt][nt], a[mt], b[nt]);
        }
    }

#pragma unroll
    for (int mt = 0; mt < 2; mt++)
#pragma unroll
        for (int nt = 0; nt < 8; nt++) {
            int row = bm + warp_m + mt * 16 + tr;
            int col = bn + warp_n + nt * 8 + 2 * tc;
            *(float2*)(C + (size_t)row * ldc + col) =
                make_float2(acc[mt][nt][0], acc[mt][nt][1]);
            *(float2*)(C + (size_t)(row + 8) * ldc + col) =
                make_float2(acc[mt][nt][2], acc[mt][nt][3]);
        }
}

// ---------------------------------------------------------------------------
// fp16 tensor-core causal GQA flash attention (unchanged from R11).
// ---------------------------------------------------------------------------
#define QS_ST   68
#define KW_     36
#define VW_     20
#define KS_OFFW (128 * QS_ST)
#define VS_OFFW (KS_OFFW + 2 * 32 * KW_)
#define FA_SMW  (VS_OFFW + 2 * 64 * VW_)    // 13568 words = 54272 B

__global__ __launch_bounds__(256, 2) void flash_f16() {
    extern __shared__ uint32_t smw[];
    float* Qs = (float*)smw;
    const int tid = threadIdx.x;
    const int w = tid >> 5, lane = tid & 31;
    const int tr = lane >> 2, tc = lane & 3;
    const int h = blockIdx.y;
    const int q0 = blockIdx.x * 128;
    const int kvh = h >> 2;
    const uint32_t sb = smem_u32(smw);

    const __half* Kg = g_Kh + kvh * HD_;
    const __half* Vg = g_Vth + (size_t)kvh * HD_ * SEQ_;

    {
        int kr = tid >> 3, kq = tid & 7;
        cpasync16(sb + (KS_OFFW + kr * KW_ + kq * 4) * 4,
                  Kg + (size_t)kr * 512 + kq * 8);
        int vr = tid >> 2, vq = tid & 3;
        cpasync16(sb + (VS_OFFW + vr * VW_ + vq * 4) * 4,
                  Vg + (size_t)vr * SEQ_ + vq * 8);
        CP_COMMIT();
    }

    {
        const float* Qgp = g_QKV + (size_t)q0 * DQKV_ + h * HD_;
#pragma unroll
        for (int i = 0; i < 8; i++) {
            int idx = tid + i * 256;
            int row = idx >> 4, c4 = idx & 15;
            *(float4*)&Qs[row * QS_ST + c4 * 4] =
                *(const float4*)(Qgp + (size_t)row * DQKV_ + c4 * 4);
        }
    }
    __syncthreads();

    uint32_t q[4][4];
    {
        const float scale = 0.125f;
        const float* q0p = Qs + (w * 16 + tr) * QS_ST;
        const float* q1p = q0p + 8 * QS_ST;
#pragma unroll
        for (int kk = 0; kk < 4; kk++) {
            int c = 16 * kk + 2 * tc;
            q[kk][0] = packh2(q0p[c] * scale, q0p[c + 1] * scale);
            q[kk][1] = packh2(q1p[c] * scale, q1p[c + 1] * scale);
            q[kk][2] = packh2(q0p[c + 8] * scale, q0p[c + 9] * scale);
            q[kk][3] = packh2(q1p[c + 8] * scale, q1p[c + 9] * scale);
        }
    }

    float o[8][4];
#pragma unroll
    for (int nf = 0; nf < 8; nf++)
#pragma unroll
        for (int r = 0; r < 4; r++) o[nf][r] = 0.f;
    float m0 = -1e30f, m1 = -1e30f, l0 = 0.f, l1 = 0.f;

    const int ntiles = (q0 + 128) / 32;

    for (int t = 0; t < ntiles; t++) {
        const int k0 = t * 32;
        if (t + 1 < ntiles) {
            const int kn = (t + 1) * 32;
            const int buf = (t + 1) & 1;
            int kr = tid >> 3, kq = tid & 7;
            cpasync16(sb + (KS_OFFW + (buf * 32 + kr) * KW_ + kq * 4) * 4,
                      Kg + (size_t)(kn + kr) * 512 + kq * 8);
            int vr = tid >> 2, vq = tid & 3;
            cpasync16(sb + (VS_OFFW + (buf * 64 + vr) * VW_ + vq * 4) * 4,
                      Vg + (size_t)vr * SEQ_ + kn + vq * 8);
            CP_COMMIT();
            CP_WAIT(1);
        } else {
            CP_WAIT(0);
        }
        __syncthreads();

        if (k0 <= q0 + w * 16 + 15) {
            const uint32_t* Kt = smw + KS_OFFW + (t & 1) * 32 * KW_;
            const uint32_t* Vt = smw + VS_OFFW + (t & 1) * 64 * VW_;

            float s[4][4];
#pragma unroll
            for (int nf = 0; nf < 4; nf++) {
                s[nf][0] = s[nf][1] = s[nf][2] = s[nf][3] = 0.f;
                const uint32_t* bp = Kt + (nf * 8 + tr) * KW_ + tc;
#pragma unroll
                for (int kk = 0; kk < 4; kk++) {
                    uint32_t b[2] = { bp[kk * 8], bp[kk * 8 + 4] };
                    mma_f16(s[nf], q[kk], b);
                }
            }

            if (k0 + 31 > q0 + w * 16) {
                const int r0 = q0 + w * 16 + tr, r1 = r0 + 8;
                const int cb = k0 + 2 * tc;
#pragma unroll
                for (int nf = 0; nf < 4; nf++) {
                    int c0 = cb + nf * 8, c1 = c0 + 1;
                    if (c0 > r0) s[nf][0] = -1e30f;
                    if (c1 > r0) s[nf][1] = -1e30f;
                    if (c0 > r1) s[nf][2] = -1e30f;
                    if (c1 > r1) s[nf][3] = -1e30f;
                }
            }

            float t0 = fmaxf(fmaxf(s[0][0], s[0][1]), fmaxf(s[1][0], s[1][1]));
            t0 = fmaxf(t0, fmaxf(fmaxf(s[2][0], s[2][1]), fmaxf(s[3][0], s[3][1])));
            float t1 = fmaxf(fmaxf(s[0][2], s[0][3]), fmaxf(s[1][2], s[1][3]));
            t1 = fmaxf(t1, fmaxf(fmaxf(s[2][2], s[2][3]), fmaxf(s[3][2], s[3][3])));
            t0 = fmaxf(t0, __shfl_xor_sync(0xFFFFFFFFu, t0, 1));
            t0 = fmaxf(t0, __shfl_xor_sync(0xFFFFFFFFu, t0, 2));
            t1 = fmaxf(t1, __shfl_xor_sync(0xFFFFFFFFu, t1, 1));
            t1 = fmaxf(t1, __shfl_xor_sync(0xFFFFFFFFu, t1, 2));
            const float mt0 = fmaxf(m0, t0), mt1 = fmaxf(m1, t1);
            const float corr0 = __expf(m0 - mt0), corr1 = __expf(m1 - mt1);
            m0 = mt0; m1 = mt1;

            float pv[4][4];
            float sum0 = 0.f, sum1 = 0.f;
#pragma unroll
            for (int nf = 0; nf < 4; nf++) {
                pv[nf][0] = __expf(s[nf][0] - mt0);
                pv[nf][1] = __expf(s[nf][1] - mt0);
                pv[nf][2] = __expf(s[nf][2] - mt1);
                pv[nf][3] = __expf(s[nf][3] - mt1);
                sum0 += pv[nf][0] + pv[nf][1];
                sum1 += pv[nf][2] + pv[nf][3];
            }
            sum0 += __shfl_xor_sync(0xFFFFFFFFu, sum0, 1);
            sum0 += __shfl_xor_sync(0xFFFFFFFFu, sum0, 2);
            sum1 += __shfl_xor_sync(0xFFFFFFFFu, sum1, 1);
            sum1 += __shfl_xor_sync(0xFFFFFFFFu, sum1, 2);
            l0 = l0 * corr0 + sum0;
            l1 = l1 * corr1 + sum1;

#pragma unroll
            for (int nf = 0; nf < 8; nf++) {
                o[nf][0] *= corr0; o[nf][1] *= corr0;
                o[nf][2] *= corr1; o[nf][3] *= corr1;
            }

#pragma unroll
            for (int kkp = 0; kkp < 2; kkp++) {
                uint32_t a[4] = {
                    packh2(pv[2 * kkp][0],     pv[2 * kkp][1]),
                    packh2(pv[2 * kkp][2],     pv[2 * kkp][3]),
                    packh2(pv[2 * kkp + 1][0], pv[2 * kkp + 1][1]),
                    packh2(pv[2 * kkp + 1][2], pv[2 * kkp + 1][3])
                };
#pragma unroll
                for (int nt = 0; nt < 8; nt++) {
                    const uint32_t* vp = Vt + (nt * 8 + tr) * VW_ + kkp * 8 + tc;
                    uint32_t b[2] = { vp[0], vp[4] };
                    mma_f16(o[nt], a, b);
                }
            }
        }
        __syncthreads();
    }

    const float inv0 = 1.f / l0, inv1 = 1.f / l1;
    const int r0 = q0 + w * 16 + tr;
    uint32_t* Og = (uint32_t*)(g_Ah + (size_t)r0 * DOUT_ + h * HD_ + 2 * tc);
    uint32_t* Og8 = (uint32_t*)(g_Ah + (size_t)(r0 + 8) * DOUT_ + h * HD_ + 2 * tc);
#pragma unroll
    for (int nf = 0; nf < 8; nf++) {
        Og[nf * 4]  = packh2(o[nf][0] * inv0, o[nf][1] * inv0);
        Og8[nf * 4] = packh2(o[nf][2] * inv1, o[nf][3] * inv1);
    }
}

// ---------------------------------------------------------------------------
extern "C" void kernel_launch(void* const* d_in, const int* in_sizes, int n_in,
                              void* d_out, int out_size) {
    const float* x    = (const float*)d_in[0];
    const float* cosp = (const float*)d_in[1];
    const float* sinp = (const float*)d_in[2];
    const float* wq   = (const float*)d_in[3];
    const float* wk   = (const float*)d_in[4];
    const float* wv   = (const float*)d_in[5];
    const float* wo   = (const float*)d_in[6];
    const float* qw   = (const float*)d_in[7];
    const float* kw   = (const float*)d_in[8];
    float* out = (float*)d_out;

    float *QKV;
    __half *xh, *wth, *woth, *Kh, *Ah;
    cudaGetSymbolAddress((void**)&xh,   g_xh);
    cudaGetSymbolAddress((void**)&wth,  g_wth);
    cudaGetSymbolAddress((void**)&woth, g_woth);
    cudaGetSymbolAddress((void**)&QKV,  g_QKV);
    cudaGetSymbolAddress((void**)&Kh,   g_Kh);
    cudaGetSymbolAddress((void**)&Ah,   g_Ah);

    const int gsmem = GNSTG_ * SSTG_W * 4;    // 61440 B
    cudaFuncSetAttribute(gemm_f16, cudaFuncAttributeMaxDynamicSharedMemorySize, gsmem);
    const int fsmem = FA_SMW * 4;             // 54272 B
    cudaFuncSetAttribute(flash_f16, cudaFuncAttributeMaxDynamicSharedMemorySize, fsmem);

    // Prep: x -> fp16; weights transpose -> fp16
    cvt_h<<<(SEQ_ * DIN_ / 2 + 255) / 256, 256>>>(x, xh, SEQ_ * DIN_ / 2);
    tposer3<<<dim3(64, DIN_ / 32, 3), dim3(32, 8)>>>(wq, wk, wv, wth);
    tposer<<<dim3(2048 / 32, DOUT_ / 32), dim3(32, 8)>>>(wo, 2048, woth, 0);

    // Fused QKV projection (fp16 tensor cores, fp32 out), 64x128 tiles
    gemm_f16<<<dim3(DQKV_ / 128, SEQ_ / 64), 128, gsmem>>>(xh, wth, QKV, DQKV_);

    // RMSNorm + RoPE: Q in place fp32; K -> fp16 g_Kh. V -> transposed fp16.
    norm_rope<<<(SEQ_ * NH_ * 32) / 256, 256>>>(QKV, qw, cosp, sinp, NH_, DQKV_, (half*)0);
    norm_rope<<<(SEQ_ * NKV_ * 32) / 256, 256>>>(QKV + 2048, kw, cosp, sinp, NKV_, DQKV_, Kh);
    vtpose<<<dim3(HD_ / 32, SEQ_ / 32, NKV_), dim3(32, 8)>>>();

    // Tensor-core causal GQA attention (fp16), writes fp16 g_Ah
    flash_f16<<<dim3(SEQ_ / 128, NH_), 256, fsmem>>>();

    // Output projection (fp16 tensor cores, fp32 out), 64x128 tiles
    gemm_f16<<<dim3(DIN_ / 128, SEQ_ / 64), 128, gsmem>>>(Ah, woth, out, DIN_);
}